// round 9
// baseline (speedup 1.0000x reference)
#include <cuda_runtime.h>

// Problem constants
constexpr int Bn   = 128;
constexpr int Ln   = 336;
constexpr int Nn   = 321;
constexpr int En   = 128;
constexpr int LATn = 64;

constexpr int HN    = Bn * Nn * En;    // 5,259,264
constexpr int LATSZ = Bn * Nn * LATn;  // 2,629,632

// Scratch: x transposed to [B, N, L] (55 MB, static device global — allowed)
__device__ static float g_xp[(size_t)Bn * Nn * Ln];

// ---------------------------------------------------------------------------
// f32x2 packed-math helpers
// ---------------------------------------------------------------------------
typedef unsigned long long u64t;

__device__ __forceinline__ u64t ffma2(u64t a, u64t b, u64t c) {
    u64t d;
    asm("fma.rn.f32x2 %0, %1, %2, %3;" : "=l"(d) : "l"(a), "l"(b), "l"(c));
    return d;
}
__device__ __forceinline__ u64t dup2(float w) {
    u64t d;
    asm("mov.b64 %0, {%1, %1};" : "=l"(d) : "f"(w));
    return d;
}
__device__ __forceinline__ float2 unpk(u64t v) {
    float2 r;
    asm("mov.b64 {%0, %1}, %2;" : "=f"(r.x), "=f"(r.y) : "l"(v));
    return r;
}

// ---------------------------------------------------------------------------
// Kernel 1: transpose x [B, L, N] -> g_xp [B, N, L]
// ---------------------------------------------------------------------------
__global__ void transpose_kernel(const float* __restrict__ x) {
    __shared__ float tile[32][33];
    const int b  = blockIdx.z;
    const int n0 = blockIdx.x * 32;
    const int l0 = blockIdx.y * 32;

#pragma unroll
    for (int i = 0; i < 4; i++) {
        int l  = l0 + threadIdx.y + i * 8;
        int nn = n0 + threadIdx.x;
        if (l < Ln && nn < Nn)
            tile[threadIdx.y + i * 8][threadIdx.x] = x[((size_t)b * Ln + l) * Nn + nn];
    }
    __syncthreads();
#pragma unroll
    for (int i = 0; i < 4; i++) {
        int nn = n0 + threadIdx.y + i * 8;
        int l  = l0 + threadIdx.x;
        if (nn < Nn && l < Ln)
            g_xp[((size_t)b * Nn + nn) * Ln + l] = tile[threadIdx.x][threadIdx.y + i * 8];
    }
}

// ---------------------------------------------------------------------------
// Kernel 2: embed GEMM, grid (Nn, Bn/64). Tile M=64(b) x N=128(e), K=336.
//   h[b,e] = sum_l xp[b,n,l]*W_embed[n,l,e] + b_embed ; h_hat = sigmoid(tx)*h
// A staged in smem PRE-DUPLICATED as f32x2; thread tile 4x8 (acc 4x4 pairs).
// Per k-step: 4 LDS.128 + 16 FFMA2, zero MOVs. ~75 regs -> no spills.
// Prefetch address is CLAMPED (not branched) -> no guard predicates in loop.
// ---------------------------------------------------------------------------
constexpr int KT = 16;
constexpr int BM = 64;

__global__ void __launch_bounds__(256, 2) embed_kernel(
    const float* __restrict__ W_embed, const float* __restrict__ b_embed,
    const float* __restrict__ time_x,
    float* __restrict__ h_out, float* __restrict__ hhat_out)
{
    __shared__ u64t  xs2[KT][BM];    // 8 KB : (x,x) duplicated pairs, [k][m]
    __shared__ float ws [KT][En];    // 8 KB : [k][e]

    const int n  = blockIdx.x;
    const int b0 = blockIdx.y * BM;
    const int t  = threadIdx.x;
    // compute mapping: 16 m-tiles(4) x 16 e-tiles(8)
    const int te = t & 15, tm = t >> 4;
    const int m_base = tm * 4, e_base = te * 8;
    // A-fill: thread -> (row mf in 0..63, k-quad kq in {0,4,8,12})
    const int mf = t >> 2;
    const int kq = (t & 3) * 4;
    // W-fill: thread -> (k row kwf in 0..15, e-oct ewf)
    const int kwf = t >> 4;
    const int ewf = (t & 15) * 8;

    const float* xrow  = g_xp + ((size_t)(b0 + mf) * Nn + n) * Ln;
    const float* wbase = W_embed + (size_t)n * Ln * En;

    u64t acc[4][4];
#pragma unroll
    for (int i = 0; i < 4; i++)
#pragma unroll
        for (int j = 0; j < 4; j++) acc[i][j] = 0ULL;

    // prologue: tile 0 into registers
    float4 xa = *(const float4*)(xrow + kq);
    float4 wa = *(const float4*)(wbase + (size_t)kwf * En + ewf);
    float4 wb = *(const float4*)(wbase + (size_t)kwf * En + ewf + 4);

    for (int kt = 0; kt < Ln; kt += KT) {
        xs2[kq + 0][mf] = dup2(xa.x);
        xs2[kq + 1][mf] = dup2(xa.y);
        xs2[kq + 2][mf] = dup2(xa.z);
        xs2[kq + 3][mf] = dup2(xa.w);
        *(float4*)&ws[kwf][ewf]     = wa;
        *(float4*)&ws[kwf][ewf + 4] = wb;
        __syncthreads();

        // prefetch next tile into registers (overlaps compute).
        // Address clamped to the last valid tile: the extra (discarded) load
        // on the final iteration re-reads in-bounds memory -> no branch.
        {
            int ktn = kt + KT;
            ktn = (ktn < Ln) ? ktn : (Ln - KT);
            xa = *(const float4*)(xrow + ktn + kq);
            wa = *(const float4*)(wbase + (size_t)(ktn + kwf) * En + ewf);
            wb = *(const float4*)(wbase + (size_t)(ktn + kwf) * En + ewf + 4);
        }

#pragma unroll
        for (int kk = 0; kk < KT; kk++) {
            ulonglong2 x01 = *(const ulonglong2*)&xs2[kk][m_base];
            ulonglong2 x23 = *(const ulonglong2*)&xs2[kk][m_base + 2];
            ulonglong2 w03 = *(const ulonglong2*)&ws[kk][e_base];
            ulonglong2 w47 = *(const ulonglong2*)&ws[kk][e_base + 4];
            u64t xd[4]  = {x01.x, x01.y, x23.x, x23.y};
            u64t wpr[4] = {w03.x, w03.y, w47.x, w47.y};
#pragma unroll
            for (int i = 0; i < 4; i++)
#pragma unroll
                for (int j = 0; j < 4; j++)
                    acc[i][j] = ffma2(wpr[j], xd[i], acc[i][j]);
        }
        __syncthreads();
    }

    // epilogue: bias + h, sigmoid(time_x)*h
    float4 ba = *(const float4*)(b_embed + n * En + e_base);
    float4 bb = *(const float4*)(b_embed + n * En + e_base + 4);
#pragma unroll
    for (int i = 0; i < 4; i++) {
        const size_t idx = ((size_t)(b0 + m_base + i) * Nn + n) * En + e_base;
        float2 p0 = unpk(acc[i][0]), p1 = unpk(acc[i][1]);
        float2 p2 = unpk(acc[i][2]), p3 = unpk(acc[i][3]);
        float4 h0 = {p0.x + ba.x, p0.y + ba.y, p1.x + ba.z, p1.y + ba.w};
        float4 h1 = {p2.x + bb.x, p2.y + bb.y, p3.x + bb.z, p3.y + bb.w};
        *(float4*)(h_out + idx)     = h0;
        *(float4*)(h_out + idx + 4) = h1;
        float4 t0 = *(const float4*)(time_x + idx);
        float4 t1 = *(const float4*)(time_x + idx + 4);
        float4 g0 = {h0.x / (1.0f + __expf(-t0.x)), h0.y / (1.0f + __expf(-t0.y)),
                     h0.z / (1.0f + __expf(-t0.z)), h0.w / (1.0f + __expf(-t0.w))};
        float4 g1 = {h1.x / (1.0f + __expf(-t1.x)), h1.y / (1.0f + __expf(-t1.y)),
                     h1.z / (1.0f + __expf(-t1.z)), h1.w / (1.0f + __expf(-t1.w))};
        *(float4*)(hhat_out + idx)     = g0;
        *(float4*)(hhat_out + idx + 4) = g1;
    }
}

// ---------------------------------------------------------------------------
// Kernel 3: heads GEMM, grid (Nn, Bn/64). Tile 64(b) x 128(mu64|var64), K=128.
// ---------------------------------------------------------------------------
__global__ void __launch_bounds__(256, 2) heads_kernel(
    const float* __restrict__ W_mu, const float* __restrict__ b_mu,
    const float* __restrict__ W_var, const float* __restrict__ b_var,
    const float* __restrict__ hhat,
    float* __restrict__ mu_out, float* __restrict__ var_out)
{
    __shared__ u64t  xs2[KT][BM];
    __shared__ float ws [KT][128];   // [k][ mu cols 0..63 | var cols 64..127 ]

    const int n  = blockIdx.x;
    const int b0 = blockIdx.y * BM;
    const int t  = threadIdx.x;
    const int te = t & 15, tm = t >> 4;
    const int m_base = tm * 4, e_base = te * 8;
    const int mf = t >> 2;
    const int kq = (t & 3) * 4;
    const int kwf = t >> 4;
    const int cwf = (t & 15) * 8;

    const float* arow = hhat + ((size_t)(b0 + mf) * Nn + n) * En;
    const float* wsrc = (cwf < 64)
        ? (W_mu  + ((size_t)n * En) * LATn + cwf)
        : (W_var + ((size_t)n * En) * LATn + (cwf - 64));

    u64t acc[4][4];
#pragma unroll
    for (int i = 0; i < 4; i++)
#pragma unroll
        for (int j = 0; j < 4; j++) acc[i][j] = 0ULL;

    float4 xa = *(const float4*)(arow + kq);
    float4 wa = *(const float4*)(wsrc + (size_t)kwf * LATn);
    float4 wb = *(const float4*)(wsrc + (size_t)kwf * LATn + 4);

    for (int kt = 0; kt < En; kt += KT) {
        xs2[kq + 0][mf] = dup2(xa.x);
        xs2[kq + 1][mf] = dup2(xa.y);
        xs2[kq + 2][mf] = dup2(xa.z);
        xs2[kq + 3][mf] = dup2(xa.w);
        *(float4*)&ws[kwf][cwf]     = wa;
        *(float4*)&ws[kwf][cwf + 4] = wb;
        __syncthreads();

        {
            int ktn = kt + KT;
            ktn = (ktn < En) ? ktn : (En - KT);
            xa = *(const float4*)(arow + ktn + kq);
            wa = *(const float4*)(wsrc + (size_t)(ktn + kwf) * LATn);
            wb = *(const float4*)(wsrc + (size_t)(ktn + kwf) * LATn + 4);
        }

#pragma unroll
        for (int kk = 0; kk < KT; kk++) {
            ulonglong2 x01 = *(const ulonglong2*)&xs2[kk][m_base];
            ulonglong2 x23 = *(const ulonglong2*)&xs2[kk][m_base + 2];
            ulonglong2 w03 = *(const ulonglong2*)&ws[kk][e_base];
            ulonglong2 w47 = *(const ulonglong2*)&ws[kk][e_base + 4];
            u64t xd[4]  = {x01.x, x01.y, x23.x, x23.y};
            u64t wpr[4] = {w03.x, w03.y, w47.x, w47.y};
#pragma unroll
            for (int i = 0; i < 4; i++)
#pragma unroll
                for (int j = 0; j < 4; j++)
                    acc[i][j] = ffma2(wpr[j], xd[i], acc[i][j]);
        }
        __syncthreads();
    }

    // epilogue: te<8 -> mu cols, te>=8 -> var cols
    const bool   is_mu = (te < 8);
    const int    col0  = is_mu ? e_base : (e_base - 64);
    const float* bsrc  = is_mu ? (b_mu + n * LATn + col0) : (b_var + n * LATn + col0);
    float* __restrict__ dst = is_mu ? mu_out : var_out;
    float4 ba = *(const float4*)(bsrc);
    float4 bb = *(const float4*)(bsrc + 4);
#pragma unroll
    for (int i = 0; i < 4; i++) {
        const size_t idx = ((size_t)(b0 + m_base + i) * Nn + n) * LATn + col0;
        float2 p0 = unpk(acc[i][0]), p1 = unpk(acc[i][1]);
        float2 p2 = unpk(acc[i][2]), p3 = unpk(acc[i][3]);
        float4 o0 = {p0.x + ba.x, p0.y + ba.y, p1.x + ba.z, p1.y + ba.w};
        float4 o1 = {p2.x + bb.x, p2.y + bb.y, p3.x + bb.z, p3.y + bb.w};
        *(float4*)(dst + idx)     = o0;
        *(float4*)(dst + idx + 4) = o1;
    }
}

// ---------------------------------------------------------------------------
// Launch
// ---------------------------------------------------------------------------
extern "C" void kernel_launch(void* const* d_in, const int* in_sizes, int n_in,
                              void* d_out, int out_size) {
    const float* x       = (const float*)d_in[0];
    const float* time_x  = (const float*)d_in[1];
    const float* W_embed = (const float*)d_in[2];
    const float* b_embed = (const float*)d_in[3];
    const float* W_mu    = (const float*)d_in[4];
    const float* b_mu    = (const float*)d_in[5];
    const float* W_var   = (const float*)d_in[6];
    const float* b_var   = (const float*)d_in[7];

    float* out  = (float*)d_out;
    float* h    = out;
    float* hhat = out + HN;
    float* mu   = out + 2 * HN;
    float* var  = out + 2 * HN + LATSZ;

    dim3 tgrid((Nn + 31) / 32, (Ln + 31) / 32, Bn);
    transpose_kernel<<<tgrid, dim3(32, 8)>>>(x);

    embed_kernel<<<dim3(Nn, Bn / BM), 256>>>(W_embed, b_embed, time_x, h, hhat);

    heads_kernel<<<dim3(Nn, Bn / BM), 256>>>(W_mu, b_mu, W_var, b_var, hhat, mu, var);
}

// round 10
// speedup vs baseline: 1.2844x; 1.2844x over previous
#include <cuda_runtime.h>

// Problem constants
constexpr int Bn   = 128;
constexpr int Ln   = 336;
constexpr int Nn   = 321;
constexpr int En   = 128;
constexpr int LATn = 64;

constexpr int HN    = Bn * Nn * En;    // 5,259,264
constexpr int LATSZ = Bn * Nn * LATn;  // 2,629,632

// Scratch: x transposed to [B, N, L] (55 MB, static device global — allowed)
__device__ static float g_xp[(size_t)Bn * Nn * Ln];

// ---------------------------------------------------------------------------
// f32x2 packed-math helpers
// ---------------------------------------------------------------------------
typedef unsigned long long u64t;

__device__ __forceinline__ u64t ffma2(u64t a, u64t b, u64t c) {
    u64t d;
    asm("fma.rn.f32x2 %0, %1, %2, %3;" : "=l"(d) : "l"(a), "l"(b), "l"(c));
    return d;
}
__device__ __forceinline__ u64t bcast2(float w) {
    u64t d;
    asm("mov.b64 %0, {%1, %1};" : "=l"(d) : "f"(w));
    return d;
}
__device__ __forceinline__ float2 unpk(u64t v) {
    float2 r;
    asm("mov.b64 {%0, %1}, %2;" : "=f"(r.x), "=f"(r.y) : "l"(v));
    return r;
}
__device__ __forceinline__ u64t pack2(float lo, float hi) {
    u64t d;
    asm("mov.b64 %0, {%1, %2};" : "=l"(d) : "f"(lo), "f"(hi));
    return d;
}

// ---------------------------------------------------------------------------
// Kernel 1: transpose x [B, L, N] -> g_xp [B, N, L]  (unchanged, ~22us)
// ---------------------------------------------------------------------------
__global__ void transpose_kernel(const float* __restrict__ x) {
    __shared__ float tile[32][33];
    const int b  = blockIdx.z;
    const int n0 = blockIdx.x * 32;
    const int l0 = blockIdx.y * 32;

#pragma unroll
    for (int i = 0; i < 4; i++) {
        int l  = l0 + threadIdx.y + i * 8;
        int nn = n0 + threadIdx.x;
        if (l < Ln && nn < Nn)
            tile[threadIdx.y + i * 8][threadIdx.x] = x[((size_t)b * Ln + l) * Nn + nn];
    }
    __syncthreads();
#pragma unroll
    for (int i = 0; i < 4; i++) {
        int nn = n0 + threadIdx.y + i * 8;
        int l  = l0 + threadIdx.x;
        if (nn < Nn && l < Ln)
            g_xp[((size_t)b * Nn + nn) * Ln + l] = tile[threadIdx.x][threadIdx.y + i * 8];
    }
}

// ---------------------------------------------------------------------------
// Kernel 2 (FUSED): per (n, 64-batch-slab) CTA.
//   Phase 1 (R3 structure, LK=56): h = xp @ W_embed + b_embed
//            epilogue: write h, h_hat = sigmoid(time_x)*h  (gmem + smem hsT)
//   Phase 2: mu/var = hsT @ [W_mu|W_var] + bias, A resident in smem.
// ---------------------------------------------------------------------------
constexpr int BM2 = 64;   // batch rows per CTA
constexpr int LK  = 56;   // phase-1 k-tile (336 = 6*56)
constexpr int BMP = 66;   // padded row width (8B-aligned pairs, few conflicts)
constexpr int KT3 = 16;   // phase-2 k-tile (128 = 8*16)

// smem overlay (bytes):
//  phase1: xs[56][66] f32 (14784)  | ws[56][128] f32 (28672)  -> 43456
//  phase2: hsT[128][66] f32 (33792)| ws3[16][128] f32 (8192)  -> 41984
constexpr int SM_XS   = 0;
constexpr int SM_WS   = 14784;
constexpr int SM_HST  = 0;
constexpr int SM_WS3  = 33792;
constexpr int SM_BYTES = 43456;

__global__ void __launch_bounds__(256, 2) fused_kernel(
    const float* __restrict__ W_embed, const float* __restrict__ b_embed,
    const float* __restrict__ time_x,
    const float* __restrict__ W_mu, const float* __restrict__ b_mu,
    const float* __restrict__ W_var, const float* __restrict__ b_var,
    float* __restrict__ h_out, float* __restrict__ hhat_out,
    float* __restrict__ mu_out, float* __restrict__ var_out)
{
    __shared__ __align__(16) char smem[SM_BYTES];
    float (*xs)[BMP]  = (float (*)[BMP])(smem + SM_XS);    // [LK][BMP]
    float (*ws)[En]   = (float (*)[En]) (smem + SM_WS);    // [LK][128]
    float (*hsT)[BMP] = (float (*)[BMP])(smem + SM_HST);   // [128][BMP]
    float (*ws3)[128] = (float (*)[128])(smem + SM_WS3);   // [KT3][128]

    const int n    = blockIdx.x;
    const int b0   = blockIdx.y * BM2;
    const int t    = threadIdx.x;
    const int lane = t & 31;
    const int wid  = t >> 5;
    const int m_base = wid * 8;

    // ===================== Phase 1: embed GEMM (R3 structure) ==============
    u64t acc[4][4];
#pragma unroll
    for (int p = 0; p < 4; p++)
#pragma unroll
        for (int j = 0; j < 4; j++) acc[p][j] = 0ULL;

    for (int kt = 0; kt < Ln; kt += LK) {
        // fill xs: 64 x 56 (coalesced reads along L)
#pragma unroll
        for (int i = 0; i < (BM2 * LK) / 256; i++) {
            int idx = t + i * 256;
            int m = idx / LK;
            int kk = idx - m * LK;
            xs[kk][m] = g_xp[((size_t)(b0 + m) * Nn + n) * Ln + kt + kk];
        }
        // fill ws: 56 x 128 (fully coalesced)
#pragma unroll
        for (int i = 0; i < (LK * En) / 256; i++) {
            int idx = t + i * 256;
            int kk = idx >> 7;
            int e  = idx & 127;
            ws[kk][e] = W_embed[((size_t)n * Ln + kt + kk) * En + e];
        }
        __syncthreads();

#pragma unroll
        for (int kk = 0; kk < LK; kk++) {
            u64t xpair[4];
#pragma unroll
            for (int p = 0; p < 4; p++)
                xpair[p] = *reinterpret_cast<const u64t*>(&xs[kk][m_base + 2 * p]);
#pragma unroll
            for (int j = 0; j < 4; j++) {
                u64t w2 = bcast2(ws[kk][lane + 32 * j]);
#pragma unroll
                for (int p = 0; p < 4; p++)
                    acc[p][j] = ffma2(xpair[p], w2, acc[p][j]);
            }
        }
        __syncthreads();
    }

    // Phase-1 epilogue: bias + h -> gmem ; h_hat -> gmem AND smem hsT[e][m]
#pragma unroll
    for (int j = 0; j < 4; j++) {
        const int e = lane + 32 * j;
        const float bias = b_embed[n * En + e];
#pragma unroll
        for (int p = 0; p < 4; p++) {
            float2 hv = unpk(acc[p][j]);
            const int mloc = m_base + 2 * p;
            const int b_r = b0 + mloc;
            const size_t i0 = ((size_t)b_r * Nn + n) * En + e;
            const size_t i1 = i0 + (size_t)Nn * En;
            float h0 = hv.x + bias;
            float h1 = hv.y + bias;
            h_out[i0] = h0;
            h_out[i1] = h1;
            float t0 = time_x[i0];
            float t1 = time_x[i1];
            float g0 = h0 / (1.0f + __expf(-t0));
            float g1 = h1 / (1.0f + __expf(-t1));
            hhat_out[i0] = g0;
            hhat_out[i1] = g1;
            *reinterpret_cast<u64t*>(&hsT[e][mloc]) = pack2(g0, g1);
        }
    }
    __syncthreads();   // hsT fully written before phase 2 reads

    // ===================== Phase 2: mu/var heads (A resident in hsT) =======
#pragma unroll
    for (int p = 0; p < 4; p++)
#pragma unroll
        for (int j = 0; j < 4; j++) acc[p][j] = 0ULL;

    for (int kt = 0; kt < En; kt += KT3) {
        // fill ws3: 16 k x (64 mu | 64 var)
#pragma unroll
        for (int i = 0; i < (KT3 * 128) / 256; i++) {
            int idx = t + i * 256;
            int kk = idx >> 7;
            int c  = idx & 127;
            float v;
            if (c < 64)
                v = W_mu[((size_t)n * En + kt + kk) * LATn + c];
            else
                v = W_var[((size_t)n * En + kt + kk) * LATn + (c - 64)];
            ws3[kk][c] = v;
        }
        __syncthreads();

#pragma unroll
        for (int kk = 0; kk < KT3; kk++) {
            u64t xpair[4];
#pragma unroll
            for (int p = 0; p < 4; p++)
                xpair[p] = *reinterpret_cast<const u64t*>(&hsT[kt + kk][m_base + 2 * p]);
#pragma unroll
            for (int j = 0; j < 4; j++) {
                u64t w2 = bcast2(ws3[kk][lane + 32 * j]);
#pragma unroll
                for (int p = 0; p < 4; p++)
                    acc[p][j] = ffma2(xpair[p], w2, acc[p][j]);
            }
        }
        __syncthreads();
    }

    // Phase-2 epilogue: j=0,1 -> mu cols, j=2,3 -> var cols
#pragma unroll
    for (int j = 0; j < 4; j++) {
        const int c = lane + 32 * j;
        const bool is_mu = (c < 64);
        const int col = is_mu ? c : (c - 64);
        const float bias = is_mu ? b_mu[n * LATn + col] : b_var[n * LATn + col];
        float* __restrict__ dst = is_mu ? mu_out : var_out;
#pragma unroll
        for (int p = 0; p < 4; p++) {
            float2 hv = unpk(acc[p][j]);
            const int b_r = b0 + m_base + 2 * p;
            const size_t i0 = ((size_t)b_r * Nn + n) * LATn + col;
            const size_t i1 = i0 + (size_t)Nn * LATn;
            dst[i0] = hv.x + bias;
            dst[i1] = hv.y + bias;
        }
    }
}

// ---------------------------------------------------------------------------
// Launch
// ---------------------------------------------------------------------------
extern "C" void kernel_launch(void* const* d_in, const int* in_sizes, int n_in,
                              void* d_out, int out_size) {
    const float* x       = (const float*)d_in[0];
    const float* time_x  = (const float*)d_in[1];
    const float* W_embed = (const float*)d_in[2];
    const float* b_embed = (const float*)d_in[3];
    const float* W_mu    = (const float*)d_in[4];
    const float* b_mu    = (const float*)d_in[5];
    const float* W_var   = (const float*)d_in[6];
    const float* b_var   = (const float*)d_in[7];

    float* out  = (float*)d_out;
    float* h    = out;
    float* hhat = out + HN;
    float* mu   = out + 2 * HN;
    float* var  = out + 2 * HN + LATSZ;

    dim3 tgrid((Nn + 31) / 32, (Ln + 31) / 32, Bn);
    transpose_kernel<<<tgrid, dim3(32, 8)>>>(x);

    fused_kernel<<<dim3(Nn, Bn / BM2), 256>>>(
        W_embed, b_embed, time_x, W_mu, b_mu, W_var, b_var,
        h, hhat, mu, var);
}

// round 12
// speedup vs baseline: 1.5220x; 1.1850x over previous
#include <cuda_runtime.h>

// Problem constants
constexpr int Bn   = 128;
constexpr int Ln   = 336;
constexpr int Nn   = 321;
constexpr int En   = 128;
constexpr int LATn = 64;

constexpr int HN    = Bn * Nn * En;    // 5,259,264
constexpr int LATSZ = Bn * Nn * LATn;  // 2,629,632

// Scratch: x transposed to [B, N, L] (55 MB, static device global — allowed)
__device__ static float g_xp[(size_t)Bn * Nn * Ln];

// ---------------------------------------------------------------------------
// f32x2 packed-math helpers
// ---------------------------------------------------------------------------
typedef unsigned long long u64t;

__device__ __forceinline__ u64t ffma2(u64t a, u64t b, u64t c) {
    u64t d;
    asm("fma.rn.f32x2 %0, %1, %2, %3;" : "=l"(d) : "l"(a), "l"(b), "l"(c));
    return d;
}
__device__ __forceinline__ u64t bcast2(float w) {
    u64t d;
    asm("mov.b64 %0, {%1, %1};" : "=l"(d) : "f"(w));
    return d;
}
__device__ __forceinline__ float2 unpk(u64t v) {
    float2 r;
    asm("mov.b64 {%0, %1}, %2;" : "=f"(r.x), "=f"(r.y) : "l"(v));
    return r;
}
__device__ __forceinline__ u64t pack2(float lo, float hi) {
    u64t d;
    asm("mov.b64 %0, {%1, %2};" : "=l"(d) : "f"(lo), "f"(hi));
    return d;
}

// ---------------------------------------------------------------------------
// Kernel 1: transpose x [B, L, N] -> g_xp [B, N, L]  (unchanged, ~22us)
// ---------------------------------------------------------------------------
__global__ void transpose_kernel(const float* __restrict__ x) {
    __shared__ float tile[32][33];
    const int b  = blockIdx.z;
    const int n0 = blockIdx.x * 32;
    const int l0 = blockIdx.y * 32;

#pragma unroll
    for (int i = 0; i < 4; i++) {
        int l  = l0 + threadIdx.y + i * 8;
        int nn = n0 + threadIdx.x;
        if (l < Ln && nn < Nn)
            tile[threadIdx.y + i * 8][threadIdx.x] = x[((size_t)b * Ln + l) * Nn + nn];
    }
    __syncthreads();
#pragma unroll
    for (int i = 0; i < 4; i++) {
        int nn = n0 + threadIdx.y + i * 8;
        int l  = l0 + threadIdx.x;
        if (nn < Nn && l < Ln)
            g_xp[((size_t)b * Nn + nn) * Ln + l] = tile[threadIdx.x][threadIdx.y + i * 8];
    }
}

// ---------------------------------------------------------------------------
// Kernel 2 (FUSED): per (n, 64-batch-slab) CTA.
//   Phase 1 (LK=56): h = xp @ W_embed + b_embed
//            epilogue: write h, h_hat = sigmoid(time_x)*h  (gmem + smem hsT)
//   Phase 2: mu/var = hsT @ [W_mu|W_var] + bias, A resident in smem.
// Changes vs R10: occupancy cap 2 -> 3 (regs <=85), float4 W fills.
// ---------------------------------------------------------------------------
constexpr int BM2 = 64;   // batch rows per CTA
constexpr int LK  = 56;   // phase-1 k-tile (336 = 6*56)
constexpr int BMP = 66;   // padded row width (8B-aligned pairs, few conflicts)
constexpr int KT3 = 16;   // phase-2 k-tile (128 = 8*16)

// smem overlay (bytes):
//  phase1: xs[56][66] f32 (14784)  | ws[56][128] f32 (28672)  -> 43456
//  phase2: hsT[128][66] f32 (33792)| ws3[16][128] f32 (8192)  -> 41984
constexpr int SM_XS   = 0;
constexpr int SM_WS   = 14784;
constexpr int SM_HST  = 0;
constexpr int SM_WS3  = 33792;
constexpr int SM_BYTES = 43456;

__global__ void __launch_bounds__(256, 3) fused_kernel(
    const float* __restrict__ W_embed, const float* __restrict__ b_embed,
    const float* __restrict__ time_x,
    const float* __restrict__ W_mu, const float* __restrict__ b_mu,
    const float* __restrict__ W_var, const float* __restrict__ b_var,
    float* __restrict__ h_out, float* __restrict__ hhat_out,
    float* __restrict__ mu_out, float* __restrict__ var_out)
{
    __shared__ __align__(16) char smem[SM_BYTES];
    float (*xs)[BMP]  = (float (*)[BMP])(smem + SM_XS);    // [LK][BMP]
    float (*ws)[En]   = (float (*)[En]) (smem + SM_WS);    // [LK][128]
    float (*hsT)[BMP] = (float (*)[BMP])(smem + SM_HST);   // [128][BMP]
    float (*ws3)[128] = (float (*)[128])(smem + SM_WS3);   // [KT3][128]

    const int n    = blockIdx.x;
    const int b0   = blockIdx.y * BM2;
    const int t    = threadIdx.x;
    const int lane = t & 31;
    const int wid  = t >> 5;
    const int m_base = wid * 8;

    // ===================== Phase 1: embed GEMM =============================
    u64t acc[4][4];
#pragma unroll
    for (int p = 0; p < 4; p++)
#pragma unroll
        for (int j = 0; j < 4; j++) acc[p][j] = 0ULL;

    for (int kt = 0; kt < Ln; kt += LK) {
        // fill xs: 64 x 56 (coalesced reads along L)
#pragma unroll
        for (int i = 0; i < (BM2 * LK) / 256; i++) {
            int idx = t + i * 256;
            int m = idx / LK;
            int kk = idx - m * LK;
            xs[kk][m] = g_xp[((size_t)(b0 + m) * Nn + n) * Ln + kt + kk];
        }
        // fill ws: 56 x 128, float4 vectorized (7 iters of LDG.128/STS.128)
#pragma unroll
        for (int i = 0; i < (LK * En) / (256 * 4); i++) {
            int idx = t + i * 256;       // quad index
            int kk = idx >> 5;           // /32 quads per row
            int e4 = (idx & 31) * 4;
            *(float4*)&ws[kk][e4] =
                *(const float4*)&W_embed[((size_t)n * Ln + kt + kk) * En + e4];
        }
        __syncthreads();

#pragma unroll
        for (int kk = 0; kk < LK; kk++) {
            u64t xpair[4];
#pragma unroll
            for (int p = 0; p < 4; p++)
                xpair[p] = *reinterpret_cast<const u64t*>(&xs[kk][m_base + 2 * p]);
#pragma unroll
            for (int j = 0; j < 4; j++) {
                u64t w2 = bcast2(ws[kk][lane + 32 * j]);
#pragma unroll
                for (int p = 0; p < 4; p++)
                    acc[p][j] = ffma2(xpair[p], w2, acc[p][j]);
            }
        }
        __syncthreads();
    }

    // Phase-1 epilogue: bias + h -> gmem ; h_hat -> gmem AND smem hsT[e][m]
#pragma unroll
    for (int j = 0; j < 4; j++) {
        const int e = lane + 32 * j;
        const float bias = b_embed[n * En + e];
#pragma unroll
        for (int p = 0; p < 4; p++) {
            float2 hv = unpk(acc[p][j]);
            const int mloc = m_base + 2 * p;
            const int b_r = b0 + mloc;
            const size_t i0 = ((size_t)b_r * Nn + n) * En + e;
            const size_t i1 = i0 + (size_t)Nn * En;
            float h0 = hv.x + bias;
            float h1 = hv.y + bias;
            h_out[i0] = h0;
            h_out[i1] = h1;
            float t0 = time_x[i0];
            float t1 = time_x[i1];
            float g0 = h0 / (1.0f + __expf(-t0));
            float g1 = h1 / (1.0f + __expf(-t1));
            hhat_out[i0] = g0;
            hhat_out[i1] = g1;
            *reinterpret_cast<u64t*>(&hsT[e][mloc]) = pack2(g0, g1);
        }
    }
    __syncthreads();   // hsT fully written before phase 2 reads

    // ===================== Phase 2: mu/var heads (A resident in hsT) =======
#pragma unroll
    for (int p = 0; p < 4; p++)
#pragma unroll
        for (int j = 0; j < 4; j++) acc[p][j] = 0ULL;

    for (int kt = 0; kt < En; kt += KT3) {
        // fill ws3: 16 k x (64 mu | 64 var), float4 vectorized (2 iters)
#pragma unroll
        for (int i = 0; i < (KT3 * 128) / (256 * 4); i++) {
            int idx = t + i * 256;       // quad index
            int kk = idx >> 5;
            int c4 = (idx & 31) * 4;
            float4 v;
            if (c4 < 64)
                v = *(const float4*)&W_mu[((size_t)n * En + kt + kk) * LATn + c4];
            else
                v = *(const float4*)&W_var[((size_t)n * En + kt + kk) * LATn + (c4 - 64)];
            *(float4*)&ws3[kk][c4] = v;
        }
        __syncthreads();

#pragma unroll
        for (int kk = 0; kk < KT3; kk++) {
            u64t xpair[4];
#pragma unroll
            for (int p = 0; p < 4; p++)
                xpair[p] = *reinterpret_cast<const u64t*>(&hsT[kt + kk][m_base + 2 * p]);
#pragma unroll
            for (int j = 0; j < 4; j++) {
                u64t w2 = bcast2(ws3[kk][lane + 32 * j]);
#pragma unroll
                for (int p = 0; p < 4; p++)
                    acc[p][j] = ffma2(xpair[p], w2, acc[p][j]);
            }
        }
        __syncthreads();
    }

    // Phase-2 epilogue: j=0,1 -> mu cols, j=2,3 -> var cols
#pragma unroll
    for (int j = 0; j < 4; j++) {
        const int c = lane + 32 * j;
        const bool is_mu = (c < 64);
        const int col = is_mu ? c : (c - 64);
        const float bias = is_mu ? b_mu[n * LATn + col] : b_var[n * LATn + col];
        float* __restrict__ dst = is_mu ? mu_out : var_out;
#pragma unroll
        for (int p = 0; p < 4; p++) {
            float2 hv = unpk(acc[p][j]);
            const int b_r = b0 + m_base + 2 * p;
            const size_t i0 = ((size_t)b_r * Nn + n) * LATn + col;
            const size_t i1 = i0 + (size_t)Nn * LATn;
            dst[i0] = hv.x + bias;
            dst[i1] = hv.y + bias;
        }
    }
}

// ---------------------------------------------------------------------------
// Launch
// ---------------------------------------------------------------------------
extern "C" void kernel_launch(void* const* d_in, const int* in_sizes, int n_in,
                              void* d_out, int out_size) {
    const float* x       = (const float*)d_in[0];
    const float* time_x  = (const float*)d_in[1];
    const float* W_embed = (const float*)d_in[2];
    const float* b_embed = (const float*)d_in[3];
    const float* W_mu    = (const float*)d_in[4];
    const float* b_mu    = (const float*)d_in[5];
    const float* W_var   = (const float*)d_in[6];
    const float* b_var   = (const float*)d_in[7];

    float* out  = (float*)d_out;
    float* h    = out;
    float* hhat = out + HN;
    float* mu   = out + 2 * HN;
    float* var  = out + 2 * HN + LATSZ;

    dim3 tgrid((Nn + 31) / 32, (Ln + 31) / 32, Bn);
    transpose_kernel<<<tgrid, dim3(32, 8)>>>(x);

    fused_kernel<<<dim3(Nn, Bn / BM2), 256>>>(
        W_embed, b_embed, time_x, W_mu, b_mu, W_var, b_var,
        h, hhat, mu, var);
}